// round 4
// baseline (speedup 1.0000x reference)
#include <cuda_runtime.h>
#include <cuda_bf16.h>

// Problem constants
#define B_   4
#define L_   256
#define DK   48      // D*K
#define D_   8
#define K_   6
#define A_   64
#define O_   64
#define DA   512     // D*A
#define CH   16      // i-values processed per phase in the pair kernel

typedef unsigned long long u64;

// Scratch (device globals: allocation-free)
__device__ float g_L1[B_ * L_ * DK];
__device__ float g_L2[B_ * L_ * DK];
__device__ float g_L3[L_ * DK];
__device__ float g_S [B_ * L_ * DA];

// ---- packed f32x2 helpers (sm_103a) ----------------------------------------
__device__ __forceinline__ u64 pk2(float lo, float hi) {
    u64 r; asm("mov.b64 %0, {%1, %2};" : "=l"(r) : "f"(lo), "f"(hi)); return r;
}
__device__ __forceinline__ void unpk2(float& lo, float& hi, u64 v) {
    asm("mov.b64 {%0, %1}, %2;" : "=f"(lo), "=f"(hi) : "l"(v));
}
__device__ __forceinline__ u64 mul2(u64 a, u64 b) {
    u64 r; asm("mul.rn.f32x2 %0, %1, %2;" : "=l"(r) : "l"(a), "l"(b)); return r;
}
__device__ __forceinline__ u64 fma2(u64 a, u64 b, u64 c) {
    u64 r; asm("fma.rn.f32x2 %0, %1, %2, %3;" : "=l"(r) : "l"(a), "l"(b), "l"(c)); return r;
}

// ---------------------------------------------------------------------------
// Kernel A: partial logits. 144 blocks x 128 threads, 16 rows/block.
//   blocks 0-63: L1, 64-127: L2, 128-143: L3.
//   Thread tile: 2 rows x 3 cols (5 LDS / 6 FMA per f).
// ---------------------------------------------------------------------------
__global__ void __launch_bounds__(128)
precompute_kernel(const float* __restrict__ in1,
                  const float* __restrict__ in2,
                  const float* __restrict__ pos,
                  const float* __restrict__ anchors) {
    __shared__ float sa[DK * 65];    // anchors slice [48][64] padded
    __shared__ float sx[16 * 65];    // x slab [16][64] padded

    const int t  = threadIdx.x;
    const int bi = blockIdx.x;

    int fo, row0;
    const float* src;
    float* dst;
    if (bi < 64)       { fo = 0;   row0 = bi * 16;         src = in1; dst = g_L1; }
    else if (bi < 128) { fo = 64;  row0 = (bi - 64) * 16;  src = in2; dst = g_L2; }
    else               { fo = 128; row0 = (bi - 128) * 16; src = pos; dst = g_L3; }

    // anchors slice: 48 x 64 = 768 float4, 6 per thread
    #pragma unroll
    for (int it = 0; it < 6; it++) {
        const int idx = t + it * 128;
        const int c   = idx >> 4;
        const int f4  = (idx & 15) << 2;
        const float4 v = *(const float4*)(anchors + c * 192 + fo + f4);
        float* d = &sa[c * 65 + f4];
        d[0] = v.x; d[1] = v.y; d[2] = v.z; d[3] = v.w;
    }
    // x slab: 16 x 64 = 256 float4, 2 per thread
    #pragma unroll
    for (int it = 0; it < 2; it++) {
        const int idx = t + it * 128;
        const int r   = idx >> 4;
        const int f4  = (idx & 15) << 2;
        const float4 v = *(const float4*)(src + (row0 + r) * 64 + f4);
        float* d = &sx[r * 65 + f4];
        d[0] = v.x; d[1] = v.y; d[2] = v.z; d[3] = v.w;
    }
    __syncthreads();

    const int rg = t & 7;     // rows rg*2, rg*2+1
    const int cg = t >> 3;    // cols cg*3 .. cg*3+2

    float acc[2][3];
    #pragma unroll
    for (int r = 0; r < 2; r++)
        #pragma unroll
        for (int c = 0; c < 3; c++) acc[r][c] = 0.f;

    const float* a0 = &sa[(cg * 3 + 0) * 65];
    const float* a1 = &sa[(cg * 3 + 1) * 65];
    const float* a2 = &sa[(cg * 3 + 2) * 65];
    const float* x0 = &sx[(rg * 2 + 0) * 65];
    const float* x1 = &sx[(rg * 2 + 1) * 65];

    #pragma unroll 8
    for (int f = 0; f < 64; f++) {
        const float av0 = a0[f], av1 = a1[f], av2 = a2[f];
        const float xv0 = x0[f], xv1 = x1[f];
        acc[0][0] = fmaf(xv0, av0, acc[0][0]);
        acc[0][1] = fmaf(xv0, av1, acc[0][1]);
        acc[0][2] = fmaf(xv0, av2, acc[0][2]);
        acc[1][0] = fmaf(xv1, av0, acc[1][0]);
        acc[1][1] = fmaf(xv1, av1, acc[1][1]);
        acc[1][2] = fmaf(xv1, av2, acc[1][2]);
    }

    #pragma unroll
    for (int r = 0; r < 2; r++)
        #pragma unroll
        for (int c = 0; c < 3; c++)
            dst[(row0 + rg * 2 + r) * DK + cg * 3 + c] = acc[r][c];
}

// ---------------------------------------------------------------------------
// Kernel B: pair loop. 1024 blocks x 512 threads, CH=16 i per phase.
//   q layout [buf][slot][d][20] (12 used, pad 20 => conflict-free LDS.128).
//   All 512 threads stage (768 sigmoid tasks, 1.5/thread), double buffered,
//   register-prefetched; consume uses packed f32x2 product tree.
// ---------------------------------------------------------------------------
__global__ void __launch_bounds__(512, 2)
pair_kernel() {
    __shared__ float sL2[DK];
    __shared__ float q[2][CH][D_][20];   // 20 KB
    __shared__ float s4[8][DA];          // 16 KB

    const int tid = threadIdx.x;
    const int b = blockIdx.x & 3;
    const int j = (L_ - 1) - (blockIdx.x >> 2);   // big-j blocks first

    if (tid < DK) sL2[tid] = g_L2[(b * L_ + j) * DK + tid];

    // consumer mapping
    const int g  = tid >> 6;
    const int tg = tid & 63;
    const int d  = tg >> 3;
    const int hi = tg & 7;

    // stager mapping: task1 = tid, task2 = tid + 512 (tid < 256)
    const int slot1 = tid / 48, dk1 = tid - slot1 * 48;
    const int d1 = dk1 / 6,  kk1 = dk1 - d1 * 6;
    float* w1 = &q[0][slot1][d1][kk1 * 2];
    const bool has2 = tid < 256;
    const int t2 = tid + 512;
    const int slot2 = t2 / 48, dk2 = t2 - slot2 * 48;
    const int d2 = dk2 / 6,  kk2 = dk2 - d2 * 6;
    float* w2 = &q[0][slot2][d2][kk2 * 2];
    const int bufStride = CH * D_ * 20;

    u64 acc01 = 0, acc23 = 0, acc45 = 0, acc67 = 0;

    const int nph = (j + CH - 1) / CH;

    const float* pL1a = &g_L1[b * L_ * DK + dk1];
    const float* pL3a = &g_L3[dk1];
    const float* pL1b = &g_L1[b * L_ * DK + dk2];
    const float* pL3b = &g_L3[dk2];

    float lg1a = 0.f, lg3a = 0.f, lg1b = 0.f, lg3b = 0.f;
    if (slot1 < j) { lg1a = pL1a[slot1 * DK]; lg3a = pL3a[(j - slot1) * DK]; }
    if (has2 && slot2 < j) { lg1b = pL1b[slot2 * DK]; lg3b = pL3b[(j - slot2) * DK]; }
    __syncthreads();                           // sL2 ready

    for (int ph = 0; ph < nph; ph++) {
        const int i0 = ph * CH;
        const int bo = (ph & 1) * bufStride;

        // stage: sigmoids from prefetched regs into q[buf]
        {
            if (i0 + slot1 < j) {
                const float logit = sL2[dk1] + lg1a + lg3a;
                const float e  = __expf(-logit);
                const float p1 = __fdividef(1.0f, 1.0f + e);
                w1[bo + 1] = p1;
                w1[bo + 0] = e * p1;
            }
            if (has2 && i0 + slot2 < j) {
                const float logit = sL2[dk2] + lg1b + lg3b;
                const float e  = __expf(-logit);
                const float p1 = __fdividef(1.0f, 1.0f + e);
                w2[bo + 1] = p1;
                w2[bo + 0] = e * p1;
            }
            // prefetch next phase
            const int na = i0 + CH + slot1;
            if (na < j) { lg1a = pL1a[na * DK]; lg3a = pL3a[(j - na) * DK]; }
            if (has2) {
                const int nb = i0 + CH + slot2;
                if (nb < j) { lg1b = pL1b[nb * DK]; lg3b = pL3b[(j - nb) * DK]; }
            }
        }
        __syncthreads();                       // q[buf] ready

        // consume: slots g and g+8, packed f32x2 product tree, 8 addr each
        #pragma unroll
        for (int half = 0; half < 2; half++) {
            const int slot = g + half * 8;
            const int i = i0 + slot;
            if (i < j) {
                const float* qd = &q[0][0][0][0] + bo + slot * (D_ * 20) + d * 20;
                const float4 Q0 = *(const float4*)(qd);      // k0:p0,p1  k1:p0,p1
                const float4 Q1 = *(const float4*)(qd + 4);  // k2:p0,p1  k3:p0,p1
                const float4 Q2 = *(const float4*)(qd + 8);  // k4:p0,p1  k5:p0,p1

                const float q3 = (hi & 1) ? Q1.w : Q1.z;
                const float q4 = (hi & 2) ? Q2.y : Q2.x;
                const float q5 = (hi & 4) ? Q2.w : Q2.z;
                const float bse = q3 * q4 * q5;

                const u64 u  = mul2(pk2(Q0.x, Q0.y), pk2(bse, bse));
                const u64 v0 = mul2(u, pk2(Q0.z, Q0.z));
                const u64 v1 = mul2(u, pk2(Q0.w, Q0.w));
                const u64 c0 = pk2(Q1.x, Q1.x);
                const u64 c1 = pk2(Q1.y, Q1.y);
                acc01 = fma2(v0, c0, acc01);
                acc23 = fma2(v1, c0, acc23);
                acc45 = fma2(v0, c1, acc45);
                acc67 = fma2(v1, c1, acc67);
            }
        }
        // single barrier per phase: store(ph+2) into this buf is ordered
        // after consume(ph) by the barrier at the top of phase ph+1.
    }

    // unpack, reduce 8 group copies, write S
    float a0, a1, a2, a3, a4, a5, a6, a7;
    unpk2(a0, a1, acc01); unpk2(a2, a3, acc23);
    unpk2(a4, a5, acc45); unpk2(a6, a7, acc67);
    float* sp = &s4[g][tg * 8];
    sp[0] = a0; sp[1] = a1; sp[2] = a2; sp[3] = a3;
    sp[4] = a4; sp[5] = a5; sp[6] = a6; sp[7] = a7;
    __syncthreads();
    float ssum = 0.f;
    #pragma unroll
    for (int gg = 0; gg < 8; gg++) ssum += s4[gg][tid];
    g_S[(b * L_ + j) * DA + tid] = ssum;
}

// ---------------------------------------------------------------------------
// Kernel C: out[row, o] = sum_da S[row, da] * W[da, o].
// 128 blocks (8 rows each) x 256 threads, split-k=2, 2x2 register tiles.
// ---------------------------------------------------------------------------
__global__ void __launch_bounds__(256)
final_gemm(const float* __restrict__ W, float* __restrict__ out) {
    __shared__ float sW[128 * 64];
    __shared__ float sS[8][132];
    __shared__ float red[128][4];

    const int t    = threadIdx.x;
    const int row0 = blockIdx.x * 8;
    const int kh   = t >> 7;
    const int u    = t & 127;
    const int tr   = u >> 5;
    const int tc   = u & 31;

    float a00 = 0.f, a01 = 0.f, a10 = 0.f, a11 = 0.f;

    for (int chnk = 0; chnk < 4; chnk++) {
        const int k0 = chnk * 128;
        const float4* Wv = (const float4*)(W + k0 * 64);
        #pragma unroll
        for (int it = 0; it < 8; it++)
            ((float4*)sW)[t + it * 256] = Wv[t + it * 256];
        {
            const int r  = t >> 5;
            const int c4 = (t & 31) << 2;
            const float4 v = *(const float4*)(&g_S[(row0 + r) * DA + k0 + c4]);
            float* dp = &sS[r][c4];
            dp[0] = v.x; dp[1] = v.y; dp[2] = v.z; dp[3] = v.w;
        }
        __syncthreads();

        const int kb = kh * 64;
        #pragma unroll 8
        for (int kk = 0; kk < 64; kk++) {
            const int k = kb + kk;
            const float2 w = *(const float2*)(&sW[k * 64 + tc * 2]);
            const float s0 = sS[tr * 2][k];
            const float s1 = sS[tr * 2 + 1][k];
            a00 = fmaf(s0, w.x, a00);
            a01 = fmaf(s0, w.y, a01);
            a10 = fmaf(s1, w.x, a10);
            a11 = fmaf(s1, w.y, a11);
        }
        __syncthreads();
    }

    if (kh == 1) {
        red[u][0] = a00; red[u][1] = a01; red[u][2] = a10; red[u][3] = a11;
    }
    __syncthreads();
    if (kh == 0) {
        a00 += red[u][0]; a01 += red[u][1]; a10 += red[u][2]; a11 += red[u][3];
        const int r = row0 + tr * 2, c = tc * 2;
        out[r * O_ + c]           = a00;
        out[r * O_ + c + 1]       = a01;
        out[(r + 1) * O_ + c]     = a10;
        out[(r + 1) * O_ + c + 1] = a11;
    }
}

// ---------------------------------------------------------------------------
extern "C" void kernel_launch(void* const* d_in, const int* in_sizes, int n_in,
                              void* d_out, int out_size) {
    const float* in1     = (const float*)d_in[0];
    const float* in2     = (const float*)d_in[1];
    const float* pos     = (const float*)d_in[2];
    const float* anchors = (const float*)d_in[3];
    const float* lut     = (const float*)d_in[4];
    float* out = (float*)d_out;

    precompute_kernel<<<144, 128>>>(in1, in2, pos, anchors);
    pair_kernel<<<1024, 512>>>();
    final_gemm<<<(B_ * L_) / 8, 256>>>(lut, out);
}

// round 5
// speedup vs baseline: 1.0709x; 1.0709x over previous
#include <cuda_runtime.h>
#include <cuda_bf16.h>

// Problem constants
#define B_   4
#define L_   256
#define DK   48      // D*K
#define D_   8
#define K_   6
#define A_   64
#define O_   64
#define DA   512     // D*A
#define CH   16      // i-values processed per phase in the pair kernel

// Scratch (device globals: allocation-free)
__device__ float g_L1[B_ * L_ * DK];
__device__ float g_L2[B_ * L_ * DK];
__device__ float g_L3[L_ * DK];
__device__ float g_S [B_ * L_ * DA];

// ---------------------------------------------------------------------------
// Kernel A: partial logits. 144 blocks x 256 threads, 16 rows/block.
//   blocks 0-63: L1, 64-127: L2, 128-143: L3.
//   Thread tile: 1 row x 3 cols (4 LDS / 3 FMA per f); 8 warps to hide latency.
// ---------------------------------------------------------------------------
__global__ void __launch_bounds__(256)
precompute_kernel(const float* __restrict__ in1,
                  const float* __restrict__ in2,
                  const float* __restrict__ pos,
                  const float* __restrict__ anchors) {
    __shared__ float sa[DK * 65];    // anchors slice [48][64] padded
    __shared__ float sx[16 * 65];    // x slab [16][64] padded

    const int t  = threadIdx.x;
    const int bi = blockIdx.x;

    int fo, row0;
    const float* src;
    float* dst;
    if (bi < 64)       { fo = 0;   row0 = bi * 16;         src = in1; dst = g_L1; }
    else if (bi < 128) { fo = 64;  row0 = (bi - 64) * 16;  src = in2; dst = g_L2; }
    else               { fo = 128; row0 = (bi - 128) * 16; src = pos; dst = g_L3; }

    // anchors slice: 48 x 64 = 768 float4, 3 per thread
    #pragma unroll
    for (int it = 0; it < 3; it++) {
        const int idx = t + it * 256;
        const int c   = idx >> 4;
        const int f4  = (idx & 15) << 2;
        const float4 v = *(const float4*)(anchors + c * 192 + fo + f4);
        float* d = &sa[c * 65 + f4];
        d[0] = v.x; d[1] = v.y; d[2] = v.z; d[3] = v.w;
    }
    // x slab: 16 x 64 = 256 float4, 1 per thread
    {
        const int r   = t >> 4;
        const int f4  = (t & 15) << 2;
        const float4 v = *(const float4*)(src + (row0 + r) * 64 + f4);
        float* d = &sx[r * 65 + f4];
        d[0] = v.x; d[1] = v.y; d[2] = v.z; d[3] = v.w;
    }
    __syncthreads();

    const int rg = t & 15;    // row
    const int cg = t >> 4;    // cols cg*3 .. cg*3+2

    float acc0 = 0.f, acc1 = 0.f, acc2 = 0.f;

    const float* a0 = &sa[(cg * 3 + 0) * 65];
    const float* a1 = &sa[(cg * 3 + 1) * 65];
    const float* a2 = &sa[(cg * 3 + 2) * 65];
    const float* x0 = &sx[rg * 65];

    #pragma unroll 16
    for (int f = 0; f < 64; f++) {
        const float xv = x0[f];
        acc0 = fmaf(xv, a0[f], acc0);
        acc1 = fmaf(xv, a1[f], acc1);
        acc2 = fmaf(xv, a2[f], acc2);
    }

    float* dp = &dst[(row0 + rg) * DK + cg * 3];
    dp[0] = acc0; dp[1] = acc1; dp[2] = acc2;
}

// ---------------------------------------------------------------------------
// Kernel B: pair loop (R2 scalar version — empirically fastest).
// 1024 blocks x 512 threads, CH=16 i per phase.
//   consume: g = tid>>6 handles i-slots g and g+8, 8 addresses each.
//   stage: 384 threads compute sigmoids for 2 slots each, double buffered,
//   register-prefetched L1/L3 loads, single barrier per phase.
// ---------------------------------------------------------------------------
__global__ void __launch_bounds__(512)
pair_kernel() {
    __shared__ float sL2[DK];
    __shared__ float q[2][CH][DK][2];   // 12 KB
    __shared__ float s4[8][DA];         // 16 KB partial-S reduce

    const int tid = threadIdx.x;
    const int bid = blockIdx.x;
    const int b = bid & 3;
    const int j = (L_ - 1) - (bid >> 2);    // big-j blocks scheduled first

    if (tid < DK) sL2[tid] = g_L2[(b * L_ + j) * DK + tid];

    const int g  = tid >> 6;
    const int tg = tid & 63;
    const int d  = tg >> 3;
    const int hi = tg & 7;

    const bool stager = tid < 8 * DK;         // 384 staging threads
    const int ii = tid / DK;                  // 0..7
    const int dk = tid - ii * DK;             // 0..47

    float acc[8];
    #pragma unroll
    for (int m = 0; m < 8; m++) acc[m] = 0.f;

    const int nph = (j + CH - 1) / CH;

    const float* pL1 = &g_L1[(b * L_) * DK + dk];
    const float* pL3 = &g_L3[dk];

    float lg1a = 0.f, lg3a = 0.f, lg1b = 0.f, lg3b = 0.f;
    if (stager) {                              // preload phase 0
        const int ia = ii, ib = ii + 8;
        if (ia < j) { lg1a = pL1[ia * DK]; lg3a = pL3[(j - ia) * DK]; }
        if (ib < j) { lg1b = pL1[ib * DK]; lg3b = pL3[(j - ib) * DK]; }
    }
    __syncthreads();                           // sL2 ready

    for (int ph = 0; ph < nph; ph++) {
        const int buf = ph & 1;
        const int i0  = ph * CH;

        if (stager) {
            const float c2 = sL2[dk];
            const int ia = i0 + ii;
            if (ia < j) {
                const float logit = c2 + lg1a + lg3a;
                const float e   = __expf(-logit);
                const float p1  = __fdividef(1.0f, 1.0f + e);
                q[buf][ii][dk][1] = p1;
                q[buf][ii][dk][0] = e * p1;
            }
            const int ib = i0 + ii + 8;
            if (ib < j) {
                const float logit = c2 + lg1b + lg3b;
                const float e   = __expf(-logit);
                const float p1  = __fdividef(1.0f, 1.0f + e);
                q[buf][ii + 8][dk][1] = p1;
                q[buf][ii + 8][dk][0] = e * p1;
            }
            // prefetch next phase
            const int na = i0 + CH + ii;
            if (na < j) { lg1a = pL1[na * DK]; lg3a = pL3[(j - na) * DK]; }
            const int nb = na + 8;
            if (nb < j) { lg1b = pL1[nb * DK]; lg3b = pL3[(j - nb) * DK]; }
        }
        __syncthreads();                       // q[buf] ready

        // consume: two i-slots (g, g+8), product tree, 8 addresses each
        #pragma unroll
        for (int half = 0; half < 2; half++) {
            const int slot = g + half * 8;
            const int i = i0 + slot;
            if (i < j) {
                const float* qb = &q[buf][slot][d * K_][0];
                const float2 q0 = *(const float2*)(qb + 0);
                const float2 q1 = *(const float2*)(qb + 2);
                const float2 q2 = *(const float2*)(qb + 4);
                const float q3 = qb[6  + (hi & 1)];
                const float q4 = qb[8  + ((hi >> 1) & 1)];
                const float q5 = qb[10 + ((hi >> 2) & 1)];

                const float bse = q3 * q4 * q5;
                const float u0 = bse * q0.x, u1 = bse * q0.y;
                const float v00 = u0 * q1.x, v01 = u1 * q1.x;
                const float v10 = u0 * q1.y, v11 = u1 * q1.y;
                acc[0] = fmaf(v00, q2.x, acc[0]);
                acc[1] = fmaf(v01, q2.x, acc[1]);
                acc[2] = fmaf(v10, q2.x, acc[2]);
                acc[3] = fmaf(v11, q2.x, acc[3]);
                acc[4] = fmaf(v00, q2.y, acc[4]);
                acc[5] = fmaf(v01, q2.y, acc[5]);
                acc[6] = fmaf(v10, q2.y, acc[6]);
                acc[7] = fmaf(v11, q2.y, acc[7]);
            }
        }
        // single barrier per phase: store(ph+2) into this buf is ordered
        // after consume(ph) by the barrier at the top of phase ph+1.
    }

    // reduce 8 group copies of S and write to global
    #pragma unroll
    for (int m = 0; m < 8; m++) s4[g][tg * 8 + m] = acc[m];
    __syncthreads();
    float ssum = 0.f;
    #pragma unroll
    for (int gg = 0; gg < 8; gg++) ssum += s4[gg][tid];
    g_S[(b * L_ + j) * DA + tid] = ssum;
}

// ---------------------------------------------------------------------------
// Kernel C: out[row, o] = sum_da S[row, da] * W[da, o].
// 128 blocks (8 rows each) x 256 threads, split-k=2, 2x2 register tiles.
// ---------------------------------------------------------------------------
__global__ void __launch_bounds__(256)
final_gemm(const float* __restrict__ W, float* __restrict__ out) {
    __shared__ float sW[128 * 64];
    __shared__ float sS[8][132];
    __shared__ float red[128][4];

    const int t    = threadIdx.x;
    const int row0 = blockIdx.x * 8;
    const int kh   = t >> 7;
    const int u    = t & 127;
    const int tr   = u >> 5;
    const int tc   = u & 31;

    float a00 = 0.f, a01 = 0.f, a10 = 0.f, a11 = 0.f;

    for (int chnk = 0; chnk < 4; chnk++) {
        const int k0 = chnk * 128;
        const float4* Wv = (const float4*)(W + k0 * 64);
        #pragma unroll
        for (int it = 0; it < 8; it++)
            ((float4*)sW)[t + it * 256] = Wv[t + it * 256];
        {
            const int r  = t >> 5;
            const int c4 = (t & 31) << 2;
            const float4 v = *(const float4*)(&g_S[(row0 + r) * DA + k0 + c4]);
            float* dp = &sS[r][c4];
            dp[0] = v.x; dp[1] = v.y; dp[2] = v.z; dp[3] = v.w;
        }
        __syncthreads();

        const int kb = kh * 64;
        #pragma unroll 8
        for (int kk = 0; kk < 64; kk++) {
            const int k = kb + kk;
            const float2 w = *(const float2*)(&sW[k * 64 + tc * 2]);
            const float s0 = sS[tr * 2][k];
            const float s1 = sS[tr * 2 + 1][k];
            a00 = fmaf(s0, w.x, a00);
            a01 = fmaf(s0, w.y, a01);
            a10 = fmaf(s1, w.x, a10);
            a11 = fmaf(s1, w.y, a11);
        }
        __syncthreads();
    }

    if (kh == 1) {
        red[u][0] = a00; red[u][1] = a01; red[u][2] = a10; red[u][3] = a11;
    }
    __syncthreads();
    if (kh == 0) {
        a00 += red[u][0]; a01 += red[u][1]; a10 += red[u][2]; a11 += red[u][3];
        const int r = row0 + tr * 2, c = tc * 2;
        out[r * O_ + c]           = a00;
        out[r * O_ + c + 1]       = a01;
        out[(r + 1) * O_ + c]     = a10;
        out[(r + 1) * O_ + c + 1] = a11;
    }
}

// ---------------------------------------------------------------------------
extern "C" void kernel_launch(void* const* d_in, const int* in_sizes, int n_in,
                              void* d_out, int out_size) {
    const float* in1     = (const float*)d_in[0];
    const float* in2     = (const float*)d_in[1];
    const float* pos     = (const float*)d_in[2];
    const float* anchors = (const float*)d_in[3];
    const float* lut     = (const float*)d_in[4];
    float* out = (float*)d_out;

    precompute_kernel<<<144, 256>>>(in1, in2, pos, anchors);
    pair_kernel<<<1024, 512>>>();
    final_gemm<<<(B_ * L_) / 8, 256>>>(lut, out);
}

// round 6
// speedup vs baseline: 1.2108x; 1.1306x over previous
#include <cuda_runtime.h>
#include <cuda_bf16.h>

// Problem constants
#define B_   4
#define L_   256
#define DK   48      // D*K
#define D_   8
#define K_   6
#define A_   64
#define O_   64
#define DA   512     // D*A

// Scratch (device globals). Logit tables pre-scaled by -log2(e) so that
// sigmoid(logit) = rcp(1 + ex2(s1+s2+s3)).
__device__ float g_L1t[DK * (B_ * L_)];   // [dk][b*256+i]   transposed
__device__ float g_L2 [(B_ * L_) * DK];   // [b*256+j][dk]   row-major
__device__ float g_L3t[DK * L_];          // [dk][delta]     transposed
__device__ float g_S  [B_ * L_ * DA];

#define NEG_LOG2E (-1.4426950408889634f)

__device__ __forceinline__ float ex2f(float x) {
    float r; asm("ex2.approx.f32 %0, %1;" : "=f"(r) : "f"(x)); return r;
}
__device__ __forceinline__ float rcpf(float x) {
    float r; asm("rcp.approx.f32 %0, %1;" : "=f"(r) : "f"(x)); return r;
}

// ---------------------------------------------------------------------------
// Kernel A: partial logits (scaled by -log2e). 144 blocks x 256 threads.
//   blocks 0-63: L1 (transposed out), 64-127: L2 (row-major out),
//   128-143: L3 (transposed out).
// ---------------------------------------------------------------------------
__global__ void __launch_bounds__(256)
precompute_kernel(const float* __restrict__ in1,
                  const float* __restrict__ in2,
                  const float* __restrict__ pos,
                  const float* __restrict__ anchors) {
    __shared__ float sa[DK * 65];
    __shared__ float sx[16 * 65];

    const int t  = threadIdx.x;
    const int bi = blockIdx.x;

    int fo, row0, mode;   // mode 0: L1t, 1: L2 row-major, 2: L3t
    const float* src;
    if (bi < 64)       { fo = 0;   row0 = bi * 16;         src = in1; mode = 0; }
    else if (bi < 128) { fo = 64;  row0 = (bi - 64) * 16;  src = in2; mode = 1; }
    else               { fo = 128; row0 = (bi - 128) * 16; src = pos; mode = 2; }

    #pragma unroll
    for (int it = 0; it < 3; it++) {
        const int idx = t + it * 256;
        const int c   = idx >> 4;
        const int f4  = (idx & 15) << 2;
        const float4 v = *(const float4*)(anchors + c * 192 + fo + f4);
        float* d = &sa[c * 65 + f4];
        d[0] = v.x; d[1] = v.y; d[2] = v.z; d[3] = v.w;
    }
    {
        const int r   = t >> 4;
        const int f4  = (t & 15) << 2;
        const float4 v = *(const float4*)(src + (row0 + r) * 64 + f4);
        float* d = &sx[r * 65 + f4];
        d[0] = v.x; d[1] = v.y; d[2] = v.z; d[3] = v.w;
    }
    __syncthreads();

    const int rg = t & 15;    // row within slab
    const int cg = t >> 4;    // cols cg*3 .. cg*3+2

    float acc0 = 0.f, acc1 = 0.f, acc2 = 0.f;
    const float* a0 = &sa[(cg * 3 + 0) * 65];
    const float* a1 = &sa[(cg * 3 + 1) * 65];
    const float* a2 = &sa[(cg * 3 + 2) * 65];
    const float* x0 = &sx[rg * 65];

    #pragma unroll 16
    for (int f = 0; f < 64; f++) {
        const float xv = x0[f];
        acc0 = fmaf(xv, a0[f], acc0);
        acc1 = fmaf(xv, a1[f], acc1);
        acc2 = fmaf(xv, a2[f], acc2);
    }
    acc0 *= NEG_LOG2E; acc1 *= NEG_LOG2E; acc2 *= NEG_LOG2E;

    const int row = row0 + rg;
    const int col = cg * 3;
    if (mode == 0) {
        g_L1t[(col + 0) * (B_ * L_) + row] = acc0;
        g_L1t[(col + 1) * (B_ * L_) + row] = acc1;
        g_L1t[(col + 2) * (B_ * L_) + row] = acc2;
    } else if (mode == 1) {
        float* dp = &g_L2[row * DK + col];
        dp[0] = acc0; dp[1] = acc1; dp[2] = acc2;
    } else {
        g_L3t[(col + 0) * L_ + row] = acc0;
        g_L3t[(col + 1) * L_ + row] = acc1;
        g_L3t[(col + 2) * L_ + row] = acc2;
    }
}

// ---------------------------------------------------------------------------
// Kernel B: warp-autonomous pair loop. 1024 blocks x 256 threads.
//   warp-task = (b, j, d); lane owns i = pass*32 + lane.
//   Per pass: 12 coalesced LDG, 6 register sigmoids (ex2+rcp), two 3-bit
//   product trees, 8x8 outer-product accumulate. No block barriers.
// ---------------------------------------------------------------------------
__global__ void __launch_bounds__(256, 2)
pair_kernel() {
    __shared__ float red[8][32][33];   // per-warp transpose-reduce scratch

    const int wid  = threadIdx.x >> 5;
    const int lane = threadIdx.x & 31;
    const int task = blockIdx.x * 8 + wid;

    const int j   = (L_ - 1) - (task >> 5);   // big-j tasks first
    const int sub = task & 31;
    const int b   = sub & 3;
    const int d   = sub >> 2;
    const int dk0 = d * K_;

    // L2 contribution for (b, j, d): 6 uniform values
    const float* l2p = &g_L2[(b * L_ + j) * DK + dk0];
    const float l2_0 = l2p[0], l2_1 = l2p[1], l2_2 = l2p[2];
    const float l2_3 = l2p[3], l2_4 = l2p[4], l2_5 = l2p[5];

    float acc[8][8];
    #pragma unroll
    for (int h = 0; h < 8; h++)
        #pragma unroll
        for (int l = 0; l < 8; l++) acc[h][l] = 0.f;

    const int base1 = b * L_;   // row offset in L1t columns
    const int npass = (j + 31) >> 5;

    for (int p = 0; p < npass; p++) {
        const int i    = p * 32 + lane;
        const int off3 = max(j - i, 0);
        const int i1   = base1 + i;

        // logit sums (pre-scaled): s_k = L2 + L1t + L3t
        const float s0 = l2_0 + g_L1t[(dk0 + 0) * (B_ * L_) + i1] + g_L3t[(dk0 + 0) * L_ + off3];
        const float s1 = l2_1 + g_L1t[(dk0 + 1) * (B_ * L_) + i1] + g_L3t[(dk0 + 1) * L_ + off3];
        const float s2 = l2_2 + g_L1t[(dk0 + 2) * (B_ * L_) + i1] + g_L3t[(dk0 + 2) * L_ + off3];
        const float s3 = l2_3 + g_L1t[(dk0 + 3) * (B_ * L_) + i1] + g_L3t[(dk0 + 3) * L_ + off3];
        const float s4 = l2_4 + g_L1t[(dk0 + 4) * (B_ * L_) + i1] + g_L3t[(dk0 + 4) * L_ + off3];
        const float s5 = l2_5 + g_L1t[(dk0 + 5) * (B_ * L_) + i1] + g_L3t[(dk0 + 5) * L_ + off3];

        // sigmoids: e = 2^s = exp(-logit); p1 = 1/(1+e); p0 = e*p1
        const float e0 = ex2f(s0), e1 = ex2f(s1), e2 = ex2f(s2);
        const float e3 = ex2f(s3), e4 = ex2f(s4), e5 = ex2f(s5);
        const float q0p1 = rcpf(1.f + e0), q0p0 = e0 * q0p1;
        const float q1p1 = rcpf(1.f + e1), q1p0 = e1 * q1p1;
        const float q2p1 = rcpf(1.f + e2), q2p0 = e2 * q2p1;
        const float q3p1 = rcpf(1.f + e3), q3p0 = e3 * q3p1;
        const float q4p1 = rcpf(1.f + e4), q4p0 = e4 * q4p1;
        const float q5p1 = rcpf(1.f + e5), q5p0 = e5 * q5p1;

        // lo tree: bits 0..2 -> (q0, q1, q2)
        const float a00 = q0p0 * q1p0, a10 = q0p1 * q1p0;
        const float a01 = q0p0 * q1p1, a11 = q0p1 * q1p1;
        float lo[8];
        lo[0] = a00 * q2p0; lo[1] = a10 * q2p0; lo[2] = a01 * q2p0; lo[3] = a11 * q2p0;
        lo[4] = a00 * q2p1; lo[5] = a10 * q2p1; lo[6] = a01 * q2p1; lo[7] = a11 * q2p1;

        // hi tree: bits 3..5 -> (q3, q4, q5), validity mask folded into q5
        const float m = (i < j) ? 1.0f : 0.0f;
        const float q5m0 = q5p0 * m, q5m1 = q5p1 * m;
        const float b00 = q3p0 * q4p0, b10 = q3p1 * q4p0;
        const float b01 = q3p0 * q4p1, b11 = q3p1 * q4p1;
        float hi[8];
        hi[0] = b00 * q5m0; hi[1] = b10 * q5m0; hi[2] = b01 * q5m0; hi[3] = b11 * q5m0;
        hi[4] = b00 * q5m1; hi[5] = b10 * q5m1; hi[6] = b01 * q5m1; hi[7] = b11 * q5m1;

        // 8x8 outer-product accumulate
        #pragma unroll
        for (int h = 0; h < 8; h++)
            #pragma unroll
            for (int l = 0; l < 8; l++)
                acc[h][l] = fmaf(hi[h], lo[l], acc[h][l]);
    }

    // warp transpose-reduce: 64 values x 32 lanes -> S[d][64]
    float (*rw)[33] = red[wid];
    const int col  = lane & 15;
    const int half = lane >> 4;
    float* sbase = &g_S[((size_t)(b * L_ + j)) * DA + d * A_];

    #pragma unroll
    for (int c = 0; c < 4; c++) {
        #pragma unroll
        for (int m2 = 0; m2 < 8; m2++) {
            rw[lane][m2]     = acc[2 * c][m2];       // a = c*16 + m2
            rw[lane][8 + m2] = acc[2 * c + 1][m2];   // a = c*16 + 8 + m2
        }
        __syncwarp();
        float sum = 0.f;
        #pragma unroll
        for (int r = 0; r < 16; r++) sum += rw[half * 16 + r][col];
        sum += __shfl_xor_sync(0xffffffffu, sum, 16);
        if (lane < 16) sbase[c * 16 + col] = sum;
        __syncwarp();
    }
}

// ---------------------------------------------------------------------------
// Kernel C: out[row, o] = sum_da S[row, da] * W[da, o].
// 128 blocks (8 rows each) x 256 threads, split-k=2, 2x2 register tiles.
// ---------------------------------------------------------------------------
__global__ void __launch_bounds__(256)
final_gemm(const float* __restrict__ W, float* __restrict__ out) {
    __shared__ float sW[128 * 64];
    __shared__ float sS[8][132];
    __shared__ float red[128][4];

    const int t    = threadIdx.x;
    const int row0 = blockIdx.x * 8;
    const int kh   = t >> 7;
    const int u    = t & 127;
    const int tr   = u >> 5;
    const int tc   = u & 31;

    float a00 = 0.f, a01 = 0.f, a10 = 0.f, a11 = 0.f;

    for (int chnk = 0; chnk < 4; chnk++) {
        const int k0 = chnk * 128;
        const float4* Wv = (const float4*)(W + k0 * 64);
        #pragma unroll
        for (int it = 0; it < 8; it++)
            ((float4*)sW)[t + it * 256] = Wv[t + it * 256];
        {
            const int r  = t >> 5;
            const int c4 = (t & 31) << 2;
            const float4 v = *(const float4*)(&g_S[(row0 + r) * DA + k0 + c4]);
            float* dp = &sS[r][c4];
            dp[0] = v.x; dp[1] = v.y; dp[2] = v.z; dp[3] = v.w;
        }
        __syncthreads();

        const int kb = kh * 64;
        #pragma unroll 8
        for (int kk = 0; kk < 64; kk++) {
            const int k = kb + kk;
            const float2 w = *(const float2*)(&sW[k * 64 + tc * 2]);
            const float s0 = sS[tr * 2][k];
            const float s1 = sS[tr * 2 + 1][k];
            a00 = fmaf(s0, w.x, a00);
            a01 = fmaf(s0, w.y, a01);
            a10 = fmaf(s1, w.x, a10);
            a11 = fmaf(s1, w.y, a11);
        }
        __syncthreads();
    }

    if (kh == 1) {
        red[u][0] = a00; red[u][1] = a01; red[u][2] = a10; red[u][3] = a11;
    }
    __syncthreads();
    if (kh == 0) {
        a00 += red[u][0]; a01 += red[u][1]; a10 += red[u][2]; a11 += red[u][3];
        const int r = row0 + tr * 2, c = tc * 2;
        out[r * O_ + c]           = a00;
        out[r * O_ + c + 1]       = a01;
        out[(r + 1) * O_ + c]     = a10;
        out[(r + 1) * O_ + c + 1] = a11;
    }
}

// ---------------------------------------------------------------------------
extern "C" void kernel_launch(void* const* d_in, const int* in_sizes, int n_in,
                              void* d_out, int out_size) {
    const float* in1     = (const float*)d_in[0];
    const float* in2     = (const float*)d_in[1];
    const float* pos     = (const float*)d_in[2];
    const float* anchors = (const float*)d_in[3];
    const float* lut     = (const float*)d_in[4];
    float* out = (float*)d_out;

    precompute_kernel<<<144, 256>>>(in1, in2, pos, anchors);
    pair_kernel<<<1024, 256>>>();
    final_gemm<<<(B_ * L_) / 8, 256>>>(lut, out);
}

// round 7
// speedup vs baseline: 1.2722x; 1.0507x over previous
#include <cuda_runtime.h>
#include <cuda_bf16.h>

// Problem constants
#define B_   4
#define L_   256
#define DK   48      // D*K
#define D_   8
#define K_   6
#define A_   64
#define O_   64
#define DA   512     // D*A

typedef unsigned long long u64;

// Scratch (device globals). Logit tables pre-scaled by -log2(e) so that
// e_k = ex2(s_k) = exp(-logit_k);  sigmoid p1 = 1/(1+e), p0 = e/(1+e).
__device__ float g_L1t[DK * (B_ * L_)];   // [dk][b*256+i]   transposed
__device__ float g_L2 [(B_ * L_) * DK];   // [b*256+j][dk]   row-major
__device__ float g_L3t[DK * L_];          // [dk][delta]     transposed
__device__ float g_S  [B_ * L_ * DA];

#define NEG_LOG2E (-1.4426950408889634f)

__device__ __forceinline__ float ex2f(float x) {
    float r; asm("ex2.approx.f32 %0, %1;" : "=f"(r) : "f"(x)); return r;
}
__device__ __forceinline__ float rcpf(float x) {
    float r; asm("rcp.approx.f32 %0, %1;" : "=f"(r) : "f"(x)); return r;
}
__device__ __forceinline__ u64 pk2(float lo, float hi) {
    u64 r; asm("mov.b64 %0, {%1, %2};" : "=l"(r) : "f"(lo), "f"(hi)); return r;
}
__device__ __forceinline__ void unpk2(float& lo, float& hi, u64 v) {
    asm("mov.b64 {%0, %1}, %2;" : "=f"(lo), "=f"(hi) : "l"(v));
}
__device__ __forceinline__ u64 mul2(u64 a, u64 b) {
    u64 r; asm("mul.rn.f32x2 %0, %1, %2;" : "=l"(r) : "l"(a), "l"(b)); return r;
}
__device__ __forceinline__ u64 fma2(u64 a, u64 b, u64 c) {
    u64 r; asm("fma.rn.f32x2 %0, %1, %2, %3;" : "=l"(r) : "l"(a), "l"(b), "l"(c)); return r;
}

// ---------------------------------------------------------------------------
// Kernel A: partial logits (scaled by -log2e). 144 blocks x 256 threads.
// ---------------------------------------------------------------------------
__global__ void __launch_bounds__(256)
precompute_kernel(const float* __restrict__ in1,
                  const float* __restrict__ in2,
                  const float* __restrict__ pos,
                  const float* __restrict__ anchors) {
    __shared__ float sa[DK * 65];
    __shared__ float sx[16 * 65];

    const int t  = threadIdx.x;
    const int bi = blockIdx.x;

    int fo, row0, mode;   // mode 0: L1t, 1: L2 row-major, 2: L3t
    const float* src;
    if (bi < 64)       { fo = 0;   row0 = bi * 16;         src = in1; mode = 0; }
    else if (bi < 128) { fo = 64;  row0 = (bi - 64) * 16;  src = in2; mode = 1; }
    else               { fo = 128; row0 = (bi - 128) * 16; src = pos; mode = 2; }

    #pragma unroll
    for (int it = 0; it < 3; it++) {
        const int idx = t + it * 256;
        const int c   = idx >> 4;
        const int f4  = (idx & 15) << 2;
        const float4 v = *(const float4*)(anchors + c * 192 + fo + f4);
        float* d = &sa[c * 65 + f4];
        d[0] = v.x; d[1] = v.y; d[2] = v.z; d[3] = v.w;
    }
    {
        const int r   = t >> 4;
        const int f4  = (t & 15) << 2;
        const float4 v = *(const float4*)(src + (row0 + r) * 64 + f4);
        float* d = &sx[r * 65 + f4];
        d[0] = v.x; d[1] = v.y; d[2] = v.z; d[3] = v.w;
    }
    __syncthreads();

    const int rg = t & 15;    // row within slab
    const int cg = t >> 4;    // cols cg*3 .. cg*3+2

    float acc0 = 0.f, acc1 = 0.f, acc2 = 0.f;
    const float* a0 = &sa[(cg * 3 + 0) * 65];
    const float* a1 = &sa[(cg * 3 + 1) * 65];
    const float* a2 = &sa[(cg * 3 + 2) * 65];
    const float* x0 = &sx[rg * 65];

    #pragma unroll 16
    for (int f = 0; f < 64; f++) {
        const float xv = x0[f];
        acc0 = fmaf(xv, a0[f], acc0);
        acc1 = fmaf(xv, a1[f], acc1);
        acc2 = fmaf(xv, a2[f], acc2);
    }
    acc0 *= NEG_LOG2E; acc1 *= NEG_LOG2E; acc2 *= NEG_LOG2E;

    const int row = row0 + rg;
    const int col = cg * 3;
    if (mode == 0) {
        g_L1t[(col + 0) * (B_ * L_) + row] = acc0;
        g_L1t[(col + 1) * (B_ * L_) + row] = acc1;
        g_L1t[(col + 2) * (B_ * L_) + row] = acc2;
    } else if (mode == 1) {
        float* dp = &g_L2[row * DK + col];
        dp[0] = acc0; dp[1] = acc1; dp[2] = acc2;
    } else {
        g_L3t[(col + 0) * L_ + row] = acc0;
        g_L3t[(col + 1) * L_ + row] = acc1;
        g_L3t[(col + 2) * L_ + row] = acc2;
    }
}

// ---------------------------------------------------------------------------
// Kernel B: warp-autonomous pair loop. 1024 blocks x 256 threads.
//   warp-task = (b, j, d); lane owns i = pass*32 + lane.
//   Z-factorized soft-LUT: prob[a] = (prod of e_k where bit_k=0) * rcp(Z),
//   Z = prod(1+e_k). One rcp per pass; trees on raw e_k; payload in f32x2.
// ---------------------------------------------------------------------------
__global__ void __launch_bounds__(256, 2)
pair_kernel() {
    __shared__ float red[8][32][33];   // per-warp transpose-reduce scratch

    const int wid  = threadIdx.x >> 5;
    const int lane = threadIdx.x & 31;
    const int task = blockIdx.x * 8 + wid;

    const int j   = (L_ - 1) - (task >> 5);   // big-j tasks first
    const int sub = task & 31;
    const int b   = sub & 3;
    const int d   = sub >> 2;
    const int dk0 = d * K_;

    // L2 contribution for (b, j, d): 6 uniform values
    const float* l2p = &g_L2[(b * L_ + j) * DK + dk0];
    const float l2_0 = l2p[0], l2_1 = l2p[1], l2_2 = l2p[2];
    const float l2_3 = l2p[3], l2_4 = l2p[4], l2_5 = l2p[5];

    u64 acc[8][4];   // [hi][lo-pair]: (a_{h,2l}, a_{h,2l+1})
    #pragma unroll
    for (int h = 0; h < 8; h++)
        #pragma unroll
        for (int l = 0; l < 4; l++) acc[h][l] = 0ull;

    const int base1 = b * L_;
    const int npass = (j + 31) >> 5;

    for (int p = 0; p < npass; p++) {
        const int i    = p * 32 + lane;
        const int off3 = max(j - i, 0);
        const int i1   = base1 + i;

        // scaled logit sums, clamped so Z cannot overflow (e_k <= 2^20)
        const float s0 = fminf(l2_0 + g_L1t[(dk0 + 0) * (B_ * L_) + i1] + g_L3t[(dk0 + 0) * L_ + off3], 20.f);
        const float s1 = fminf(l2_1 + g_L1t[(dk0 + 1) * (B_ * L_) + i1] + g_L3t[(dk0 + 1) * L_ + off3], 20.f);
        const float s2 = fminf(l2_2 + g_L1t[(dk0 + 2) * (B_ * L_) + i1] + g_L3t[(dk0 + 2) * L_ + off3], 20.f);
        const float s3 = fminf(l2_3 + g_L1t[(dk0 + 3) * (B_ * L_) + i1] + g_L3t[(dk0 + 3) * L_ + off3], 20.f);
        const float s4 = fminf(l2_4 + g_L1t[(dk0 + 4) * (B_ * L_) + i1] + g_L3t[(dk0 + 4) * L_ + off3], 20.f);
        const float s5 = fminf(l2_5 + g_L1t[(dk0 + 5) * (B_ * L_) + i1] + g_L3t[(dk0 + 5) * L_ + off3], 20.f);

        const float e0 = ex2f(s0), e1 = ex2f(s1), e2 = ex2f(s2);
        const float e3 = ex2f(s3), e4 = ex2f(s4), e5 = ex2f(s5);

        // Z = prod(1+e_k); one reciprocal, mask folded in
        const float z01 = (1.f + e0) * (1.f + e1);
        const float z23 = (1.f + e2) * (1.f + e3);
        const float z45 = (1.f + e4) * (1.f + e5);
        const float Z   = z01 * z23 * z45;
        const float m   = (i < j) ? 1.0f : 0.0f;
        const float rm  = rcpf(Z) * m;

        // lo tree (bits 0..2 on e0,e1,e2; bit=1 contributes 1):
        //   lo = {e0e1e2, e1e2, e0e2, e2, e0e1, e1, e0, 1}
        const float c01 = e0 * e1;
        const u64 P01 = pk2(c01, e1);
        const u64 P23 = pk2(e0, 1.f);
        const u64 E2b = pk2(e2, e2);
        u64 LO[4];
        LO[0] = mul2(P01, E2b);
        LO[1] = mul2(P23, E2b);
        LO[2] = P01;
        LO[3] = P23;

        // hi tree (bits 3..5 on e3,e4,e5), scaled by rm:
        //   hi = {e3e4e5, e4e5, e3e5, e5, e3e4, e4, e3, 1} * rm
        const float c34  = e3 * e4;
        const float e5rm = e5 * rm;
        float hi[8];
        hi[0] = c34 * e5rm;
        hi[1] = e4 * e5rm;
        hi[2] = e3 * e5rm;
        hi[3] = e5rm;
        hi[4] = c34 * rm;
        hi[5] = e4 * rm;
        hi[6] = e3 * rm;
        hi[7] = rm;

        // payload: 8x8 outer product, f32x2 packed (32 FFMA2)
        #pragma unroll
        for (int h = 0; h < 8; h++) {
            const u64 hb = pk2(hi[h], hi[h]);
            acc[h][0] = fma2(hb, LO[0], acc[h][0]);
            acc[h][1] = fma2(hb, LO[1], acc[h][1]);
            acc[h][2] = fma2(hb, LO[2], acc[h][2]);
            acc[h][3] = fma2(hb, LO[3], acc[h][3]);
        }
    }

    // unpack to scalar [h][l]
    float av[8][8];
    #pragma unroll
    for (int h = 0; h < 8; h++)
        #pragma unroll
        for (int l = 0; l < 4; l++)
            unpk2(av[h][2 * l], av[h][2 * l + 1], acc[h][l]);

    // warp transpose-reduce: 64 values x 32 lanes -> S[d][64]
    float (*rw)[33] = red[wid];
    const int col  = lane & 15;
    const int half = lane >> 4;
    float* sbase = &g_S[((size_t)(b * L_ + j)) * DA + d * A_];

    #pragma unroll
    for (int c = 0; c < 4; c++) {
        #pragma unroll
        for (int m2 = 0; m2 < 8; m2++) {
            rw[lane][m2]     = av[2 * c][m2];       // a = c*16 + m2
            rw[lane][8 + m2] = av[2 * c + 1][m2];   // a = c*16 + 8 + m2
        }
        __syncwarp();
        float sum = 0.f;
        #pragma unroll
        for (int r = 0; r < 16; r++) sum += rw[half * 16 + r][col];
        sum += __shfl_xor_sync(0xffffffffu, sum, 16);
        if (lane < 16) sbase[c * 16 + col] = sum;
        __syncwarp();
    }
}

// ---------------------------------------------------------------------------
// Kernel C: out[row, o] = sum_da S[row, da] * W[da, o].
// 128 blocks (8 rows each) x 256 threads, split-k=2, 2x2 register tiles.
// ---------------------------------------------------------------------------
__global__ void __launch_bounds__(256)
final_gemm(const float* __restrict__ W, float* __restrict__ out) {
    __shared__ float sW[128 * 64];
    __shared__ float sS[8][132];
    __shared__ float red[128][4];

    const int t    = threadIdx.x;
    const int row0 = blockIdx.x * 8;
    const int kh   = t >> 7;
    const int u    = t & 127;
    const int tr   = u >> 5;
    const int tc   = u & 31;

    float a00 = 0.f, a01 = 0.f, a10 = 0.f, a11 = 0.f;

    for (int chnk = 0; chnk < 4; chnk++) {
        const int k0 = chnk * 128;
        const float4* Wv = (const float4*)(W + k0 * 64);
        #pragma unroll
        for (int it = 0; it < 8; it++)
            ((float4*)sW)[t + it * 256] = Wv[t + it * 256];
        {
            const int r  = t >> 5;
            const int c4 = (t & 31) << 2;
            const float4 v = *(const float4*)(&g_S[(row0 + r) * DA + k0 + c4]);
            float* dp = &sS[r][c4];
            dp[0] = v.x; dp[1] = v.y; dp[2] = v.z; dp[3] = v.w;
        }
        __syncthreads();

        const int kb = kh * 64;
        #pragma unroll 8
        for (int kk = 0; kk < 64; kk++) {
            const int k = kb + kk;
            const float2 w = *(const float2*)(&sW[k * 64 + tc * 2]);
            const float s0 = sS[tr * 2][k];
            const float s1 = sS[tr * 2 + 1][k];
            a00 = fmaf(s0, w.x, a00);
            a01 = fmaf(s0, w.y, a01);
            a10 = fmaf(s1, w.x, a10);
            a11 = fmaf(s1, w.y, a11);
        }
        __syncthreads();
    }

    if (kh == 1) {
        red[u][0] = a00; red[u][1] = a01; red[u][2] = a10; red[u][3] = a11;
    }
    __syncthreads();
    if (kh == 0) {
        a00 += red[u][0]; a01 += red[u][1]; a10 += red[u][2]; a11 += red[u][3];
        const int r = row0 + tr * 2, c = tc * 2;
        out[r * O_ + c]           = a00;
        out[r * O_ + c + 1]       = a01;
        out[(r + 1) * O_ + c]     = a10;
        out[(r + 1) * O_ + c + 1] = a11;
    }
}

// ---------------------------------------------------------------------------
extern "C" void kernel_launch(void* const* d_in, const int* in_sizes, int n_in,
                              void* d_out, int out_size) {
    const float* in1     = (const float*)d_in[0];
    const float* in2     = (const float*)d_in[1];
    const float* pos     = (const float*)d_in[2];
    const float* anchors = (const float*)d_in[3];
    const float* lut     = (const float*)d_in[4];
    float* out = (float*)d_out;

    precompute_kernel<<<144, 256>>>(in1, in2, pos, anchors);
    pair_kernel<<<1024, 256>>>();
    final_gemm<<<(B_ * L_) / 8, 256>>>(lut, out);
}

// round 8
// speedup vs baseline: 1.2901x; 1.0140x over previous
#include <cuda_runtime.h>
#include <cuda_bf16.h>

// Problem constants
#define B_   4
#define L_   256
#define DK   48      // D*K
#define D_   8
#define K_   6
#define A_   64
#define O_   64
#define DA   512     // D*A

typedef unsigned long long u64;

// Scratch (device globals). Tables hold e-factors: E = ex2(-logit*log2e) so
// exp(-logit_total) = E1[i] * E3[j-i] * C2 (multiplicative split of the sum).
__device__ float g_E1t[DK * (B_ * L_)];   // [dk][b*256+i]   transposed
__device__ float g_C2 [(B_ * L_) * DK];   // [b*256+j][dk]   row-major
__device__ float g_E3t[DK * L_];          // [dk][delta]     transposed
__device__ float g_S  [B_ * L_ * DA];

#define NEG_LOG2E (-1.4426950408889634f)

__device__ __forceinline__ float ex2f(float x) {
    float r; asm("ex2.approx.f32 %0, %1;" : "=f"(r) : "f"(x)); return r;
}
__device__ __forceinline__ float rcpf(float x) {
    float r; asm("rcp.approx.f32 %0, %1;" : "=f"(r) : "f"(x)); return r;
}
__device__ __forceinline__ u64 pk2(float lo, float hi) {
    u64 r; asm("mov.b64 %0, {%1, %2};" : "=l"(r) : "f"(lo), "f"(hi)); return r;
}
__device__ __forceinline__ void unpk2(float& lo, float& hi, u64 v) {
    asm("mov.b64 {%0, %1}, %2;" : "=f"(lo), "=f"(hi) : "l"(v));
}
__device__ __forceinline__ u64 mul2(u64 a, u64 b) {
    u64 r; asm("mul.rn.f32x2 %0, %1, %2;" : "=l"(r) : "l"(a), "l"(b)); return r;
}
__device__ __forceinline__ u64 fma2(u64 a, u64 b, u64 c) {
    u64 r; asm("fma.rn.f32x2 %0, %1, %2, %3;" : "=l"(r) : "l"(a), "l"(b), "l"(c)); return r;
}

// ---------------------------------------------------------------------------
// Kernel A: partial e-factors. 288 blocks x 128 threads, 8 rows/block.
//   blocks 0-127: E1t, 128-255: C2 (row-major), 256-287: E3t.
//   Stores ex2(min(-logit*log2e, 30)).
// ---------------------------------------------------------------------------
__global__ void __launch_bounds__(128)
precompute_kernel(const float* __restrict__ in1,
                  const float* __restrict__ in2,
                  const float* __restrict__ pos,
                  const float* __restrict__ anchors) {
    __shared__ float sa[DK * 65];
    __shared__ float sx[8 * 65];

    const int t  = threadIdx.x;
    const int bi = blockIdx.x;

    int fo, row0, mode;   // mode 0: E1t, 1: C2 row-major, 2: E3t
    const float* src;
    if (bi < 128)      { fo = 0;   row0 = bi * 8;         src = in1; mode = 0; }
    else if (bi < 256) { fo = 64;  row0 = (bi - 128) * 8; src = in2; mode = 1; }
    else               { fo = 128; row0 = (bi - 256) * 8; src = pos; mode = 2; }

    // anchors slice: 48 x 64 = 768 float4, 6 per thread
    #pragma unroll
    for (int it = 0; it < 6; it++) {
        const int idx = t + it * 128;
        const int c   = idx >> 4;
        const int f4  = (idx & 15) << 2;
        const float4 v = *(const float4*)(anchors + c * 192 + fo + f4);
        float* d = &sa[c * 65 + f4];
        d[0] = v.x; d[1] = v.y; d[2] = v.z; d[3] = v.w;
    }
    // x slab: 8 x 64 = 128 float4, 1 per thread
    {
        const int r   = t >> 4;
        const int f4  = (t & 15) << 2;
        const float4 v = *(const float4*)(src + (row0 + r) * 64 + f4);
        float* d = &sx[r * 65 + f4];
        d[0] = v.x; d[1] = v.y; d[2] = v.z; d[3] = v.w;
    }
    __syncthreads();

    const int rg = t >> 4;    // row within slab (0..7)
    const int cg = t & 15;    // cols cg*3 .. cg*3+2

    float acc0 = 0.f, acc1 = 0.f, acc2 = 0.f;
    const float* a0 = &sa[(cg * 3 + 0) * 65];
    const float* a1 = &sa[(cg * 3 + 1) * 65];
    const float* a2 = &sa[(cg * 3 + 2) * 65];
    const float* x0 = &sx[rg * 65];

    #pragma unroll 16
    for (int f = 0; f < 64; f++) {
        const float xv = x0[f];
        acc0 = fmaf(xv, a0[f], acc0);
        acc1 = fmaf(xv, a1[f], acc1);
        acc2 = fmaf(xv, a2[f], acc2);
    }
    acc0 = ex2f(fminf(acc0 * NEG_LOG2E, 30.f));
    acc1 = ex2f(fminf(acc1 * NEG_LOG2E, 30.f));
    acc2 = ex2f(fminf(acc2 * NEG_LOG2E, 30.f));

    const int row = row0 + rg;
    const int col = cg * 3;
    if (mode == 0) {
        g_E1t[(col + 0) * (B_ * L_) + row] = acc0;
        g_E1t[(col + 1) * (B_ * L_) + row] = acc1;
        g_E1t[(col + 2) * (B_ * L_) + row] = acc2;
    } else if (mode == 1) {
        float* dp = &g_C2[row * DK + col];
        dp[0] = acc0; dp[1] = acc1; dp[2] = acc2;
    } else {
        g_E3t[(col + 0) * L_ + row] = acc0;
        g_E3t[(col + 1) * L_ + row] = acc1;
        g_E3t[(col + 2) * L_ + row] = acc2;
    }
}

// ---------------------------------------------------------------------------
// Kernel B: warp-autonomous pair loop. 2048 blocks x 128 threads (5/SM).
//   warp-task = (b, j, d); lane owns i = pass*32 + lane.
//   e_k = E1_k[i] * E3_k[j-i] * C2_k (no MUFU ex2 in the loop);
//   Z-factorized soft-LUT with one rcp; f32x2-packed 8x8 outer product.
// ---------------------------------------------------------------------------
__global__ void __launch_bounds__(128, 5)
pair_kernel() {
    __shared__ float red[4][32][33];   // per-warp transpose-reduce scratch

    const int wid  = threadIdx.x >> 5;
    const int lane = threadIdx.x & 31;
    const int task = blockIdx.x * 4 + wid;

    const int j   = (L_ - 1) - (task >> 5);   // big-j tasks first
    const int sub = task & 31;
    const int b   = sub & 3;
    const int d   = sub >> 2;
    const int dk0 = d * K_;

    // C2 contribution for (b, j, d): 6 uniform values
    const float* c2p = &g_C2[(b * L_ + j) * DK + dk0];
    const float c2_0 = c2p[0], c2_1 = c2p[1], c2_2 = c2p[2];
    const float c2_3 = c2p[3], c2_4 = c2p[4], c2_5 = c2p[5];

    u64 acc[8][4];   // [hi][lo-pair]
    #pragma unroll
    for (int h = 0; h < 8; h++)
        #pragma unroll
        for (int l = 0; l < 4; l++) acc[h][l] = 0ull;

    const float* e1b = &g_E1t[dk0 * (B_ * L_) + b * L_];
    const float* e3b = &g_E3t[dk0 * L_];
    const int npass = (j + 31) >> 5;

    for (int p = 0; p < npass; p++) {
        const int i    = p * 32 + lane;
        const int off3 = max(j - i, 0);

        // e_k = E1*E3*C2, clamped to 2^20 so Z stays finite
        const float e0 = fminf(e1b[0 * (B_ * L_) + i] * (e3b[0 * L_ + off3] * c2_0), 1048576.f);
        const float e1 = fminf(e1b[1 * (B_ * L_) + i] * (e3b[1 * L_ + off3] * c2_1), 1048576.f);
        const float e2 = fminf(e1b[2 * (B_ * L_) + i] * (e3b[2 * L_ + off3] * c2_2), 1048576.f);
        const float e3 = fminf(e1b[3 * (B_ * L_) + i] * (e3b[3 * L_ + off3] * c2_3), 1048576.f);
        const float e4 = fminf(e1b[4 * (B_ * L_) + i] * (e3b[4 * L_ + off3] * c2_4), 1048576.f);
        const float e5 = fminf(e1b[5 * (B_ * L_) + i] * (e3b[5 * L_ + off3] * c2_5), 1048576.f);

        // Z = prod(1+e_k); one reciprocal, validity mask folded in
        const float z01 = (1.f + e0) * (1.f + e1);
        const float z23 = (1.f + e2) * (1.f + e3);
        const float z45 = (1.f + e4) * (1.f + e5);
        const float Z   = z01 * z23 * z45;
        const float m   = (i < j) ? 1.0f : 0.0f;
        const float rm  = rcpf(Z) * m;

        // lo tree (bits 0..2 on e0,e1,e2; bit=1 contributes 1):
        //   lo = {e0e1e2, e1e2, e0e2, e2, e0e1, e1, e0, 1}
        const float c01 = e0 * e1;
        const u64 P01 = pk2(c01, e1);
        const u64 P23 = pk2(e0, 1.f);
        const u64 E2b = pk2(e2, e2);
        u64 LO[4];
        LO[0] = mul2(P01, E2b);
        LO[1] = mul2(P23, E2b);
        LO[2] = P01;
        LO[3] = P23;

        // hi tree (bits 3..5 on e3,e4,e5), scaled by rm
        const float c34  = e3 * e4;
        const float e5rm = e5 * rm;
        float hi[8];
        hi[0] = c34 * e5rm;
        hi[1] = e4 * e5rm;
        hi[2] = e3 * e5rm;
        hi[3] = e5rm;
        hi[4] = c34 * rm;
        hi[5] = e4 * rm;
        hi[6] = e3 * rm;
        hi[7] = rm;

        // 8x8 outer product, f32x2 packed (32 FFMA2)
        #pragma unroll
        for (int h = 0; h < 8; h++) {
            const u64 hb = pk2(hi[h], hi[h]);
            acc[h][0] = fma2(hb, LO[0], acc[h][0]);
            acc[h][1] = fma2(hb, LO[1], acc[h][1]);
            acc[h][2] = fma2(hb, LO[2], acc[h][2]);
            acc[h][3] = fma2(hb, LO[3], acc[h][3]);
        }
    }

    // unpack to scalar [h][l]
    float av[8][8];
    #pragma unroll
    for (int h = 0; h < 8; h++)
        #pragma unroll
        for (int l = 0; l < 4; l++)
            unpk2(av[h][2 * l], av[h][2 * l + 1], acc[h][l]);

    // warp transpose-reduce: 64 values x 32 lanes -> S[d][64]
    float (*rw)[33] = red[wid];
    const int col  = lane & 15;
    const int half = lane >> 4;
    float* sbase = &g_S[((size_t)(b * L_ + j)) * DA + d * A_];

    #pragma unroll
    for (int c = 0; c < 4; c++) {
        #pragma unroll
        for (int m2 = 0; m2 < 8; m2++) {
            rw[lane][m2]     = av[2 * c][m2];
            rw[lane][8 + m2] = av[2 * c + 1][m2];
        }
        __syncwarp();
        float sum = 0.f;
        #pragma unroll
        for (int r = 0; r < 16; r++) sum += rw[half * 16 + r][col];
        sum += __shfl_xor_sync(0xffffffffu, sum, 16);
        if (lane < 16) sbase[c * 16 + col] = sum;
        __syncwarp();
    }
}

// ---------------------------------------------------------------------------
// Kernel C: out[row, o] = sum_da S[row, da] * W[da, o].
// 128 blocks (8 rows each) x 256 threads, split-k=2, 2x2 register tiles.
// ---------------------------------------------------------------------------
__global__ void __launch_bounds__(256)
final_gemm(const float* __restrict__ W, float* __restrict__ out) {
    __shared__ float sW[128 * 64];
    __shared__ float sS[8][132];
    __shared__ float red[128][4];

    const int t    = threadIdx.x;
    const int row0 = blockIdx.x * 8;
    const int kh   = t >> 7;
    const int u    = t & 127;
    const int tr   = u >> 5;
    const int tc   = u & 31;

    float a00 = 0.f, a01 = 0.f, a10 = 0.f, a11 = 0.f;

    for (int chnk = 0; chnk < 4; chnk++) {
        const int k0 = chnk * 128;
        const float4* Wv = (const float4*)(W + k0 * 64);
        #pragma unroll
        for (int it = 0; it < 8; it++)
            ((float4*)sW)[t + it * 256] = Wv[t + it * 256];
        {
            const int r  = t >> 5;
            const int c4 = (t & 31) << 2;
            const float4 v = *(const float4*)(&g_S[(row0 + r) * DA + k0 + c4]);
            float* dp = &sS[r][c4];
            dp[0] = v.x; dp[1] = v.y; dp[2] = v.z; dp[3] = v.w;
        }
        __syncthreads();

        const int kb = kh * 64;
        #pragma unroll 8
        for (int kk = 0; kk < 64; kk++) {
            const int k = kb + kk;
            const float2 w = *(const float2*)(&sW[k * 64 + tc * 2]);
            const float s0 = sS[tr * 2][k];
            const float s1 = sS[tr * 2 + 1][k];
            a00 = fmaf(s0, w.x, a00);
            a01 = fmaf(s0, w.y, a01);
            a10 = fmaf(s1, w.x, a10);
            a11 = fmaf(s1, w.y, a11);
        }
        __syncthreads();
    }

    if (kh == 1) {
        red[u][0] = a00; red[u][1] = a01; red[u][2] = a10; red[u][3] = a11;
    }
    __syncthreads();
    if (kh == 0) {
        a00 += red[u][0]; a01 += red[u][1]; a10 += red[u][2]; a11 += red[u][3];
        const int r = row0 + tr * 2, c = tc * 2;
        out[r * O_ + c]           = a00;
        out[r * O_ + c + 1]       = a01;
        out[(r + 1) * O_ + c]     = a10;
        out[(r + 1) * O_ + c + 1] = a11;
    }
}

// ---------------------------------------------------------------------------
extern "C" void kernel_launch(void* const* d_in, const int* in_sizes, int n_in,
                              void* d_out, int out_size) {
    const float* in1     = (const float*)d_in[0];
    const float* in2     = (const float*)d_in[1];
    const float* pos     = (const float*)d_in[2];
    const float* anchors = (const float*)d_in[3];
    const float* lut     = (const float*)d_in[4];
    float* out = (float*)d_out;

    precompute_kernel<<<288, 128>>>(in1, in2, pos, anchors);
    pair_kernel<<<2048, 128>>>();
    final_gemm<<<(B_ * L_) / 8, 256>>>(lut, out);
}